// round 9
// baseline (speedup 1.0000x reference)
#include <cuda_runtime.h>

#define N_NODES 50000
#define N_EDGES 200000
#define C 32
#define ND 75
#define ED 12
#define NL 3
#define NG 500
#define HID 5
#define BN_EPS 1e-5f

#define COEF_BLOCKS 782
#define INIT_BLOCKS 400

// Scratch (no allocations allowed)
__device__ __align__(128) float g_h[N_NODES * C];         // layer-0 features
__device__ __align__(128) float g_hn[N_NODES * C];        // normalized h (layers 1,2)
__device__ __align__(128) float g_agg[N_NODES * C];       // conv accumulator
__device__ __align__(128) float g_v[N_NODES * 6 * C];     // v[n,k,d]
__device__ __align__(128) float g_coef[NL * N_EDGES * 8]; // edge MLP coefs, padded
__device__ float g_stats[2 * C];                          // BN sum / sumsq

// ---- packed fp32x2 helpers (sm_103a) ----
__device__ __forceinline__ void fma2(unsigned long long& acc, unsigned long long a,
                                     unsigned long long b) {
    asm("fma.rn.f32x2 %0, %1, %2, %0;" : "+l"(acc) : "l"(a), "l"(b));
}
__device__ __forceinline__ unsigned long long pack2(float v) {
    unsigned long long r;
    asm("mov.b64 %0, {%1, %1};" : "=l"(r) : "f"(v));
    return r;
}
__device__ __forceinline__ void red_add_v4(float* addr, float4 v) {
    asm volatile("red.global.add.v4.f32 [%0], {%1, %2, %3, %4};"
                 :: "l"(addr), "f"(v.x), "f"(v.y), "f"(v.z), "f"(v.w) : "memory");
}

// ---------------------------------------------------------------------------
// Fused init + coef.
// Blocks [0, COEF_BLOCKS): per-edge MLP coefs for all 3 layers.
// Blocks [COEF_BLOCKS, COEF_BLOCKS+INIT_BLOCKS): h = leaky(x@linW + lin_b),
//   8-lane layout: warp = 4 nodes x 8 float4 slices; x values broadcast in L1.
// ---------------------------------------------------------------------------
__global__ void __launch_bounds__(256) k_ic(const float* __restrict__ x,
                                            const float* __restrict__ W,
                                            const float* __restrict__ b,
                                            const float* __restrict__ ea,
                                            const float* __restrict__ W1,
                                            const float* __restrict__ b1) {
    int tid = threadIdx.x;
    if (blockIdx.x < COEF_BLOCKS) {
        __shared__ float sW1[NL * ED * HID];
        __shared__ float sb1[NL * HID];
        if (tid < NL * ED * HID) sW1[tid] = W1[tid];
        if (tid < NL * HID) sb1[tid] = b1[tid];
        __syncthreads();
        for (int e = blockIdx.x * 256 + tid; e < N_EDGES; e += COEF_BLOCKS * 256) {
            float eav[ED];
            const float4* ear = (const float4*)(ea + (size_t)e * ED);
#pragma unroll
            for (int q = 0; q < 3; q++) {
                float4 v = ear[q];
                eav[4 * q] = v.x; eav[4 * q + 1] = v.y;
                eav[4 * q + 2] = v.z; eav[4 * q + 3] = v.w;
            }
#pragma unroll
            for (int l = 0; l < NL; l++) {
                float out[8];
#pragma unroll
                for (int k = 0; k < HID; k++) {
                    float s = sb1[l * HID + k];
#pragma unroll
                    for (int j = 0; j < ED; j++) s += eav[j] * sW1[(l * ED + j) * HID + k];
                    out[k] = fmaxf(s, 0.f);
                }
                out[5] = 1.f; out[6] = 0.f; out[7] = 0.f;
                float4* co = (float4*)(g_coef + ((size_t)l * N_EDGES + e) * 8);
                co[0] = make_float4(out[0], out[1], out[2], out[3]);
                co[1] = make_float4(out[4], out[5], out[6], out[7]);
            }
        }
    } else {
        __shared__ __align__(16) float sW[ND * C];
        __shared__ float sb[C];
        for (int i = tid; i < ND * C; i += 256) sW[i] = W[i];
        if (tid < C) sb[tid] = b[tid];
        __syncthreads();
        int lane = tid & 31;
        int g = lane >> 3, cb4 = (lane & 7) * 4;
        int w0 = (blockIdx.x - COEF_BLOCKS) * 8 + (tid >> 5);
        for (int grp = w0; grp < N_NODES / 4; grp += INIT_BLOCKS * 8) {
            int node = grp * 4 + g;
            const float* xr = x + (size_t)node * ND;
            unsigned long long a0 = 0ULL, a1 = 0ULL;
#pragma unroll 5
            for (int j = 0; j < ND; j++) {
                unsigned long long p = pack2(__ldg(xr + j));
                const ulonglong2* w2 = (const ulonglong2*)(sW + j * C + cb4);
                ulonglong2 ww = *w2;
                fma2(a0, p, ww.x);
                fma2(a1, p, ww.y);
            }
            float2 lo = *(float2*)&a0, hi = *(float2*)&a1;
            float v0 = lo.x + sb[cb4], v1 = lo.y + sb[cb4 + 1];
            float v2 = hi.x + sb[cb4 + 2], v3 = hi.y + sb[cb4 + 3];
            v0 = v0 > 0.f ? v0 : 0.01f * v0;
            v1 = v1 > 0.f ? v1 : 0.01f * v1;
            v2 = v2 > 0.f ? v2 : 0.01f * v2;
            v3 = v3 > 0.f ? v3 : 0.01f * v3;
            *(float4*)(g_h + (size_t)node * C + cb4) = make_float4(v0, v1, v2, v3);
        }
    }
}

// ---------------------------------------------------------------------------
// k_norm: g_hn = leaky(BN(g_agg)) using g_stats. Used as input to layers 1,2.
// ---------------------------------------------------------------------------
__global__ void __launch_bounds__(256) k_norm(const float* __restrict__ bng,
                                              const float* __restrict__ bnb) {
    __shared__ float sA[C], sB[C];
    if (threadIdx.x < C) {
        float mu = g_stats[threadIdx.x] * (1.0f / N_NODES);
        float var = g_stats[C + threadIdx.x] * (1.0f / N_NODES) - mu * mu;
        float Av = rsqrtf(var + BN_EPS) * bng[threadIdx.x];
        sA[threadIdx.x] = Av;
        sB[threadIdx.x] = bnb[threadIdx.x] - mu * Av;
    }
    __syncthreads();
    const float4* A = (const float4*)g_agg;
    float4* O = (float4*)g_hn;
    int stride = gridDim.x * blockDim.x;
    for (int i = blockIdx.x * blockDim.x + threadIdx.x; i < N_NODES * 8; i += stride) {
        int c0 = (i & 7) * 4;
        float4 v = A[i];
        v.x = v.x * sA[c0] + sB[c0];         v.x = v.x > 0.f ? v.x : 0.01f * v.x;
        v.y = v.y * sA[c0 + 1] + sB[c0 + 1]; v.y = v.y > 0.f ? v.y : 0.01f * v.y;
        v.z = v.z * sA[c0 + 2] + sB[c0 + 2]; v.z = v.z > 0.f ? v.z : 0.01f * v.z;
        v.w = v.w * sA[c0 + 3] + sB[c0 + 3]; v.w = v.w > 0.f ? v.w : 0.01f * v.w;
        O[i] = v;
    }
}

// ---------------------------------------------------------------------------
// k_v, 8-lane layout (k_edge-style): warp = (slot, 4 nodes, 8 slices).
//   slots 0..4: h @ W2[k] -> g_v ;  slot 5: h @ b2 -> g_v
//   slot 6:     h @ rootW + conv_b -> g_agg
// h loads are 8-way-broadcast L1 hits; weight LDS.128 conflict-free broadcast;
// stores fully coalesced (4 nodes x 128B contiguous per warp).
// ---------------------------------------------------------------------------
__global__ void __launch_bounds__(256) k_v(const float* __restrict__ W2,
                                           const float* __restrict__ b2,
                                           const float* __restrict__ rootW,
                                           const float* __restrict__ cbv,
                                           int layer) {
    __shared__ __align__(16) float sW[7 * C * C];   // 28 KB
    __shared__ float sCB[C];
    int tid = threadIdx.x;
    for (int i = tid; i < HID * C * C; i += 256) sW[i] = W2[i];
    for (int i = tid; i < C * C; i += 256) {
        sW[5 * C * C + i] = b2[i];
        sW[6 * C * C + i] = rootW[i];
    }
    if (tid < C) sCB[tid] = cbv[tid];
    __syncthreads();

    const float* hin = (layer == 0) ? g_h : g_hn;
    int lane = tid & 31;
    int g = lane >> 3, cb4 = (lane & 7) * 4;
    int w0 = blockIdx.x * 8 + (tid >> 5);
    const int TOT = 7 * (N_NODES / 4);   // 87500
    int wstride = gridDim.x * 8;

    for (int it = w0; it < TOT; it += wstride) {
        int slot = it % 7;
        int grp = it / 7;
        int node = grp * 4 + g;
        const float4* hr = (const float4*)(hin + (size_t)node * C);
        const float* wb = sW + slot * C * C + cb4;
        unsigned long long a0 = 0ULL, a1 = 0ULL;
#pragma unroll 2
        for (int ch = 0; ch < 8; ch++) {
            float4 hv = __ldg(hr + ch);
            {
                unsigned long long p = pack2(hv.x);
                ulonglong2 ww = *(const ulonglong2*)(wb + (ch * 4 + 0) * C);
                fma2(a0, p, ww.x); fma2(a1, p, ww.y);
            }
            {
                unsigned long long p = pack2(hv.y);
                ulonglong2 ww = *(const ulonglong2*)(wb + (ch * 4 + 1) * C);
                fma2(a0, p, ww.x); fma2(a1, p, ww.y);
            }
            {
                unsigned long long p = pack2(hv.z);
                ulonglong2 ww = *(const ulonglong2*)(wb + (ch * 4 + 2) * C);
                fma2(a0, p, ww.x); fma2(a1, p, ww.y);
            }
            {
                unsigned long long p = pack2(hv.w);
                ulonglong2 ww = *(const ulonglong2*)(wb + (ch * 4 + 3) * C);
                fma2(a0, p, ww.x); fma2(a1, p, ww.y);
            }
        }
        float2 lo = *(float2*)&a0, hi = *(float2*)&a1;
        if (slot == 6) {
            float4 r = make_float4(lo.x + sCB[cb4], lo.y + sCB[cb4 + 1],
                                   hi.x + sCB[cb4 + 2], hi.y + sCB[cb4 + 3]);
            *(float4*)(g_agg + (size_t)node * C + cb4) = r;
        } else {
            *(float4*)(g_v + (size_t)node * 192 + slot * C + cb4) =
                make_float4(lo.x, lo.y, hi.x, hi.y);
        }
    }
}

// ---------------------------------------------------------------------------
// Edge kernel, coalesced: 8 lanes per edge (warp = 4 edges).
// Block 0 zeroes g_stats for this layer's k_stats.
// ---------------------------------------------------------------------------
__global__ void __launch_bounds__(256) k_edge(const int* __restrict__ src,
                                              const int* __restrict__ dst,
                                              int layer) {
    if (blockIdx.x == 0 && threadIdx.x < 2 * C) g_stats[threadIdx.x] = 0.f;

    const float* coefL = g_coef + (size_t)layer * N_EDGES * 8;

    int lane = threadIdx.x & 31;
    int warp = (blockIdx.x * blockDim.x + threadIdx.x) >> 5;
    int group = lane >> 3;
    int d4 = lane & 7;
    int e = warp * 4 + group;
    if (e >= N_EDGES) return;

    int sn = __ldg(src + e);
    int dn = __ldg(dst + e);
    const float* cp = coefL + (size_t)e * 8;
    float4 c03 = __ldg((const float4*)cp);
    float2 c45 = __ldg((const float2*)(cp + 4));
    float coef[6] = {c03.x, c03.y, c03.z, c03.w, c45.x, c45.y};

    unsigned long long a0 = 0ULL, a1 = 0ULL;
    const float* vb = g_v + (size_t)sn * (6 * C) + d4 * 4;
#pragma unroll
    for (int k = 0; k < 6; k++) {
        float ck = coef[k];
        if (ck != 0.f) {
            ulonglong2 w = __ldg((const ulonglong2*)(vb + k * C));
            unsigned long long p = pack2(ck);
            fma2(a0, p, w.x);
            fma2(a1, p, w.y);
        }
    }

    float2 lo = *(float2*)&a0, hi = *(float2*)&a1;
    red_add_v4(g_agg + (size_t)dn * C + d4 * 4, make_float4(lo.x, lo.y, hi.x, hi.y));
}

// ---------------------------------------------------------------------------
// BN statistics over g_agg; for the last layer, blocks 0-1 also seed the
// output with pred_b (k_fin atomicAdds on top afterwards).
// ---------------------------------------------------------------------------
__global__ void __launch_bounds__(256) k_stats(float* out, const float* __restrict__ pb,
                                               int do_out) {
    if (do_out && blockIdx.x < 2) {
        int g = blockIdx.x * 256 + threadIdx.x;
        if (g < NG) out[g] = pb[0];
    }
    __shared__ float ss[2 * C];
    if (threadIdx.x < 2 * C) ss[threadIdx.x] = 0.f;
    __syncthreads();
    const float4* A = (const float4*)g_agg;
    float4 s = {0.f, 0.f, 0.f, 0.f}, q = {0.f, 0.f, 0.f, 0.f};
    int stride = gridDim.x * blockDim.x;
    for (int i = blockIdx.x * blockDim.x + threadIdx.x; i < N_NODES * 8; i += stride) {
        float4 v = A[i];
        s.x += v.x; s.y += v.y; s.z += v.z; s.w += v.w;
        q.x += v.x * v.x; q.y += v.y * v.y; q.z += v.z * v.z; q.w += v.w * v.w;
    }
#pragma unroll
    for (int off = 8; off <= 16; off <<= 1) {
        s.x += __shfl_xor_sync(0xffffffffu, s.x, off);
        s.y += __shfl_xor_sync(0xffffffffu, s.y, off);
        s.z += __shfl_xor_sync(0xffffffffu, s.z, off);
        s.w += __shfl_xor_sync(0xffffffffu, s.w, off);
        q.x += __shfl_xor_sync(0xffffffffu, q.x, off);
        q.y += __shfl_xor_sync(0xffffffffu, q.y, off);
        q.z += __shfl_xor_sync(0xffffffffu, q.z, off);
        q.w += __shfl_xor_sync(0xffffffffu, q.w, off);
    }
    int lane = threadIdx.x & 31;
    if (lane < 8) {
        int cg = lane * 4;
        atomicAdd(&ss[cg + 0], s.x); atomicAdd(&ss[cg + 1], s.y);
        atomicAdd(&ss[cg + 2], s.z); atomicAdd(&ss[cg + 3], s.w);
        atomicAdd(&ss[C + cg + 0], q.x); atomicAdd(&ss[C + cg + 1], q.y);
        atomicAdd(&ss[C + cg + 2], q.z); atomicAdd(&ss[C + cg + 3], q.w);
    }
    __syncthreads();
    if (threadIdx.x < 2 * C) atomicAdd(&g_stats[threadIdx.x], ss[threadIdx.x]);
}

// ---------------------------------------------------------------------------
// Final: BN (no leaky) + prediction dot + scatter to graphs (batch is sorted).
// Tail lanes clamp and contribute 0 (all collectives full-warp).
// ---------------------------------------------------------------------------
__global__ void __launch_bounds__(256) k_fin(const int* __restrict__ batch,
                                             const float* __restrict__ pW,
                                             const float* __restrict__ bng,
                                             const float* __restrict__ bnb,
                                             float* out) {
    __shared__ float snorm[4 * C];
    __shared__ float spw[C];
    if (threadIdx.x < C) {
        float mu = g_stats[threadIdx.x] * (1.0f / N_NODES);
        float var = g_stats[C + threadIdx.x] * (1.0f / N_NODES) - mu * mu;
        snorm[threadIdx.x] = mu;
        snorm[C + threadIdx.x] = rsqrtf(var + BN_EPS);
        snorm[2 * C + threadIdx.x] = bng[threadIdx.x];
        snorm[3 * C + threadIdx.x] = bnb[threadIdx.x];
        spw[threadIdx.x] = pW[threadIdx.x];
    }
    __syncthreads();
    int n = blockIdx.x * blockDim.x + threadIdx.x;
    bool valid = n < N_NODES;
    int nn = valid ? n : N_NODES - 1;
    const float4* ap = (const float4*)(g_agg + (size_t)nn * C);
    float s = 0.f;
#pragma unroll
    for (int q = 0; q < 8; q++) {
        float4 v = ap[q];
        float t[4] = {v.x, v.y, v.z, v.w};
#pragma unroll
        for (int r = 0; r < 4; r++) {
            int c = 4 * q + r;
            float val = (t[r] - snorm[c]) * snorm[C + c] * snorm[2 * C + c] + snorm[3 * C + c];
            s += val * spw[c];
        }
    }
    if (!valid) s = 0.f;
    int bid = batch[nn];
    int bid0 = __shfl_sync(0xffffffffu, bid, 0);
    bool uni = __all_sync(0xffffffffu, bid == bid0 && valid);
    if (uni) {
#pragma unroll
        for (int off = 16; off >= 1; off >>= 1)
            s += __shfl_xor_sync(0xffffffffu, s, off);
        if ((threadIdx.x & 31) == 0) atomicAdd(&out[bid0], s);
    } else if (valid) {
        atomicAdd(&out[bid], s);
    }
}

// ---------------------------------------------------------------------------
extern "C" void kernel_launch(void* const* d_in, const int* in_sizes, int n_in,
                              void* d_out, int out_size) {
    const float* x       = (const float*)d_in[0];
    const int*   ei      = (const int*)d_in[1];
    const float* ea      = (const float*)d_in[2];
    const int*   batch   = (const int*)d_in[3];
    const float* lin_W   = (const float*)d_in[4];
    const float* lin_b   = (const float*)d_in[5];
    const float* mes_W1  = (const float*)d_in[6];
    const float* mes_b1  = (const float*)d_in[7];
    const float* mes_W2  = (const float*)d_in[8];
    const float* mes_b2  = (const float*)d_in[9];
    const float* root_W  = (const float*)d_in[10];
    const float* conv_b  = (const float*)d_in[11];
    const float* bn_g    = (const float*)d_in[12];
    const float* bn_b    = (const float*)d_in[13];
    const float* pred_W  = (const float*)d_in[14];
    const float* pred_b  = (const float*)d_in[15];
    float* out = (float*)d_out;

    const int* src = ei;
    const int* dst = ei + N_EDGES;

    int eblocks = (N_EDGES / 4 * 32 + 255) / 256;    // 6250

    k_ic<<<COEF_BLOCKS + INIT_BLOCKS, 256>>>(x, lin_W, lin_b, ea, mes_W1, mes_b1);
    for (int l = 0; l < NL; l++) {
        if (l > 0) k_norm<<<592, 256>>>(bn_g + (l - 1) * C, bn_b + (l - 1) * C);
        k_v<<<1184, 256>>>(mes_W2 + l * HID * C * C, mes_b2 + l * C * C,
                           root_W + l * C * C, conv_b + l * C, l);
        k_edge<<<eblocks, 256>>>(src, dst, l);
        k_stats<<<592, 256>>>(out, pred_b, l == NL - 1 ? 1 : 0);
    }
    k_fin<<<(N_NODES + 255) / 256, 256>>>(batch, pred_W, bn_g + 2 * C, bn_b + 2 * C, out);
}

// round 10
// speedup vs baseline: 1.3190x; 1.3190x over previous
#include <cuda_runtime.h>

#define N_NODES 50000
#define N_EDGES 200000
#define C 32
#define ND 75
#define ED 12
#define NL 3
#define NG 500
#define HID 5
#define BN_EPS 1e-5f

// Scratch (no allocations allowed)
__device__ __align__(128) float g_hT[C * N_NODES];        // TRANSPOSED features: hT[c][n]
__device__ __align__(128) float g_agg[N_NODES * C];       // conv accumulator (row-major)
__device__ __align__(128) float g_v[N_NODES * 6 * C];     // v[n,k,d]
__device__ __align__(128) float g_coef[NL * N_EDGES * 8]; // edge MLP coefs, padded
__device__ float g_stats[2 * C];                          // BN sum / sumsq

// ---- packed fp32x2 helpers (sm_103a) ----
__device__ __forceinline__ void fma2(unsigned long long& acc, unsigned long long a,
                                     unsigned long long b) {
    asm("fma.rn.f32x2 %0, %1, %2, %0;" : "+l"(acc) : "l"(a), "l"(b));
}
__device__ __forceinline__ unsigned long long pack2(float v) {
    unsigned long long r;
    asm("mov.b64 %0, {%1, %1};" : "=l"(r) : "f"(v));
    return r;
}
__device__ __forceinline__ void red_add_v4(float* addr, float4 v) {
    asm volatile("red.global.add.v4.f32 [%0], {%1, %2, %3, %4};"
                 :: "l"(addr), "f"(v.x), "f"(v.y), "f"(v.z), "f"(v.w) : "memory");
}

// ---------------------------------------------------------------------------
// h = leaky(x @ lin_W + lin_b), written TRANSPOSED to g_hT (coalesced STG.32).
// ---------------------------------------------------------------------------
__global__ void __launch_bounds__(256) k_init(const float* __restrict__ x,
                                              const float* __restrict__ W,
                                              const float* __restrict__ b) {
    __shared__ __align__(16) float sW[ND * C];
    __shared__ float sb[C];
    for (int i = threadIdx.x; i < ND * C; i += blockDim.x) sW[i] = W[i];
    if (threadIdx.x < C) sb[threadIdx.x] = b[threadIdx.x];
    __syncthreads();
    int n = blockIdx.x * blockDim.x + threadIdx.x;
    if (n >= N_NODES) return;
    float acc[C];
#pragma unroll
    for (int d = 0; d < C; d++) acc[d] = sb[d];
    const float* xr = x + (size_t)n * ND;
#pragma unroll 5
    for (int j = 0; j < ND; j++) {
        float xv = __ldg(xr + j);
#pragma unroll
        for (int d = 0; d < C; d++) acc[d] += xv * sW[j * C + d];
    }
#pragma unroll
    for (int d = 0; d < C; d++) {
        float v = acc[d];
        v = v > 0.f ? v : 0.01f * v;
        g_hT[(size_t)d * N_NODES + n] = v;    // coalesced across the warp
    }
}

// ---------------------------------------------------------------------------
// Precompute edge-MLP coefs for ALL layers (edge_attr is layer-invariant).
// ---------------------------------------------------------------------------
__global__ void __launch_bounds__(256) k_coef(const float* __restrict__ ea,
                                              const float* __restrict__ W1,
                                              const float* __restrict__ b1) {
    __shared__ float sW1[NL * ED * HID];
    __shared__ float sb1[NL * HID];
    if (threadIdx.x < NL * ED * HID) sW1[threadIdx.x] = W1[threadIdx.x];
    if (threadIdx.x < NL * HID) sb1[threadIdx.x] = b1[threadIdx.x];
    __syncthreads();
    int e = blockIdx.x * blockDim.x + threadIdx.x;
    if (e >= N_EDGES) return;
    float eav[ED];
    const float4* ear = (const float4*)(ea + (size_t)e * ED);
#pragma unroll
    for (int q = 0; q < 3; q++) {
        float4 v = ear[q];
        eav[4 * q] = v.x; eav[4 * q + 1] = v.y; eav[4 * q + 2] = v.z; eav[4 * q + 3] = v.w;
    }
#pragma unroll
    for (int l = 0; l < NL; l++) {
        float out[8];
#pragma unroll
        for (int k = 0; k < HID; k++) {
            float s = sb1[l * HID + k];
#pragma unroll
            for (int j = 0; j < ED; j++) s += eav[j] * sW1[(l * ED + j) * HID + k];
            out[k] = fmaxf(s, 0.f);
        }
        out[5] = 1.f; out[6] = 0.f; out[7] = 0.f;
        float4* co = (float4*)(g_coef + ((size_t)l * N_EDGES + e) * 8);
        co[0] = make_float4(out[0], out[1], out[2], out[3]);
        co[1] = make_float4(out[4], out[5], out[6], out[7]);
    }
}

// ---------------------------------------------------------------------------
// k_v (R6 structure; ONLY the h-load addressing changed to transposed g_hT).
// Warp = (slot, 32 nodes), lane = node. Slots:
//   0..4: hT @ W2[k] -> g_v ; 5: hT @ b2 -> g_v ; 6: hT @ rootW + cb -> g_agg
// h loads: one coalesced LDG.32 per channel (1 line/warp vs 32 before).
// ---------------------------------------------------------------------------
__global__ void __launch_bounds__(256) k_v(const float* __restrict__ W2,
                                           const float* __restrict__ b2,
                                           const float* __restrict__ rootW,
                                           const float* __restrict__ cbv) {
    __shared__ __align__(16) float sW[7 * C * C];   // 28 KB
    __shared__ float sCB[C];
    for (int i = threadIdx.x; i < HID * C * C; i += 256) sW[i] = W2[i];
    for (int i = threadIdx.x; i < C * C; i += 256) {
        sW[5 * C * C + i] = b2[i];
        sW[6 * C * C + i] = rootW[i];
    }
    if (threadIdx.x < C) sCB[threadIdx.x] = cbv[threadIdx.x];
    __syncthreads();

    int gw = blockIdx.x * 8 + (threadIdx.x >> 5);
    int slot = gw % 7;
    int node = (gw / 7) * 32 + (threadIdx.x & 31);
    if (node >= N_NODES) return;

    unsigned long long acc[16];
#pragma unroll
    for (int j = 0; j < 16; j++) acc[j] = 0ULL;
    const float* wbase = sW + slot * C * C;
#pragma unroll 8
    for (int c = 0; c < C; c++) {
        float hc = __ldg(g_hT + (size_t)c * N_NODES + node);   // coalesced
        unsigned long long p = pack2(hc);
        const ulonglong2* wr = (const ulonglong2*)(wbase + c * C);
#pragma unroll
        for (int j = 0; j < 8; j++) {
            ulonglong2 w = wr[j];
            fma2(acc[2 * j], p, w.x);
            fma2(acc[2 * j + 1], p, w.y);
        }
    }

    if (slot == 6) {
        float4* ao = (float4*)(g_agg + (size_t)node * C);
        const float* af = (const float*)acc;
#pragma unroll
        for (int q = 0; q < 8; q++) {
            float4 v;
            v.x = af[4 * q] + sCB[4 * q];
            v.y = af[4 * q + 1] + sCB[4 * q + 1];
            v.z = af[4 * q + 2] + sCB[4 * q + 2];
            v.w = af[4 * q + 3] + sCB[4 * q + 3];
            ao[q] = v;
        }
    } else {
        float4* vo = (float4*)(g_v + (size_t)node * (6 * C) + slot * C);
        const float4* af = (const float4*)acc;
#pragma unroll
        for (int q = 0; q < 8; q++) vo[q] = af[q];
    }
}

// ---------------------------------------------------------------------------
// Edge kernel (unchanged, measured 17.4us): 8 lanes per edge (warp = 4 edges).
// Block 0 zeroes g_stats for this layer's k_stats.
// ---------------------------------------------------------------------------
__global__ void __launch_bounds__(256) k_edge(const int* __restrict__ src,
                                              const int* __restrict__ dst,
                                              int layer) {
    if (blockIdx.x == 0 && threadIdx.x < 2 * C) g_stats[threadIdx.x] = 0.f;

    const float* coefL = g_coef + (size_t)layer * N_EDGES * 8;

    int lane = threadIdx.x & 31;
    int warp = (blockIdx.x * blockDim.x + threadIdx.x) >> 5;
    int group = lane >> 3;
    int d4 = lane & 7;
    int e = warp * 4 + group;
    if (e >= N_EDGES) return;

    int sn = __ldg(src + e);
    int dn = __ldg(dst + e);
    const float* cp = coefL + (size_t)e * 8;
    float4 c03 = __ldg((const float4*)cp);
    float2 c45 = __ldg((const float2*)(cp + 4));
    float coef[6] = {c03.x, c03.y, c03.z, c03.w, c45.x, c45.y};

    unsigned long long a0 = 0ULL, a1 = 0ULL;
    const float* vb = g_v + (size_t)sn * (6 * C) + d4 * 4;
#pragma unroll
    for (int k = 0; k < 6; k++) {
        float ck = coef[k];
        if (ck != 0.f) {
            ulonglong2 w = __ldg((const ulonglong2*)(vb + k * C));
            unsigned long long p = pack2(ck);
            fma2(a0, p, w.x);
            fma2(a1, p, w.y);
        }
    }

    float2 lo = *(float2*)&a0, hi = *(float2*)&a1;
    red_add_v4(g_agg + (size_t)dn * C + d4 * 4, make_float4(lo.x, lo.y, hi.x, hi.y));
}

// ---------------------------------------------------------------------------
// BN statistics over g_agg; for the last layer, blocks 0-1 seed out with pred_b.
// ---------------------------------------------------------------------------
__global__ void __launch_bounds__(256) k_stats(float* out, const float* __restrict__ pb,
                                               int do_out) {
    if (do_out && blockIdx.x < 2) {
        int g = blockIdx.x * 256 + threadIdx.x;
        if (g < NG) out[g] = pb[0];
    }
    __shared__ float ss[2 * C];
    if (threadIdx.x < 2 * C) ss[threadIdx.x] = 0.f;
    __syncthreads();
    const float4* A = (const float4*)g_agg;
    float4 s = {0.f, 0.f, 0.f, 0.f}, q = {0.f, 0.f, 0.f, 0.f};
    int stride = gridDim.x * blockDim.x;
    for (int i = blockIdx.x * blockDim.x + threadIdx.x; i < N_NODES * 8; i += stride) {
        float4 v = A[i];
        s.x += v.x; s.y += v.y; s.z += v.z; s.w += v.w;
        q.x += v.x * v.x; q.y += v.y * v.y; q.z += v.z * v.z; q.w += v.w * v.w;
    }
#pragma unroll
    for (int off = 8; off <= 16; off <<= 1) {
        s.x += __shfl_xor_sync(0xffffffffu, s.x, off);
        s.y += __shfl_xor_sync(0xffffffffu, s.y, off);
        s.z += __shfl_xor_sync(0xffffffffu, s.z, off);
        s.w += __shfl_xor_sync(0xffffffffu, s.w, off);
        q.x += __shfl_xor_sync(0xffffffffu, q.x, off);
        q.y += __shfl_xor_sync(0xffffffffu, q.y, off);
        q.z += __shfl_xor_sync(0xffffffffu, q.z, off);
        q.w += __shfl_xor_sync(0xffffffffu, q.w, off);
    }
    int lane = threadIdx.x & 31;
    if (lane < 8) {
        int cg = lane * 4;
        atomicAdd(&ss[cg + 0], s.x); atomicAdd(&ss[cg + 1], s.y);
        atomicAdd(&ss[cg + 2], s.z); atomicAdd(&ss[cg + 3], s.w);
        atomicAdd(&ss[C + cg + 0], q.x); atomicAdd(&ss[C + cg + 1], q.y);
        atomicAdd(&ss[C + cg + 2], q.z); atomicAdd(&ss[C + cg + 3], q.w);
    }
    __syncthreads();
    if (threadIdx.x < 2 * C) atomicAdd(&g_stats[threadIdx.x], ss[threadIdx.x]);
}

// ---------------------------------------------------------------------------
// k_normT: g_hT[c][n] = leaky(BN(g_agg[n][c])). Smem-tiled transpose:
// coalesced float4 row loads, conflict-free smem (stride 33), coalesced STG.32.
// Block = 32 nodes. No warp collectives; tail guarded per element.
// ---------------------------------------------------------------------------
__global__ void __launch_bounds__(256) k_normT(const float* __restrict__ bng,
                                               const float* __restrict__ bnb) {
    __shared__ float sA[C], sB[C];
    __shared__ float st[32 * 33];
    if (threadIdx.x < C) {
        float mu = g_stats[threadIdx.x] * (1.0f / N_NODES);
        float var = g_stats[C + threadIdx.x] * (1.0f / N_NODES) - mu * mu;
        float Av = rsqrtf(var + BN_EPS) * bng[threadIdx.x];
        sA[threadIdx.x] = Av;
        sB[threadIdx.x] = bnb[threadIdx.x] - mu * Av;
    }
    __syncthreads();

    int nodeBase = blockIdx.x * 32;
    int r = threadIdx.x >> 3;        // node within tile 0..31
    int q = threadIdx.x & 7;         // float4 chunk 0..7
    int n = nodeBase + r;
    if (n < N_NODES) {
        float4 v = ((const float4*)(g_agg + (size_t)n * C))[q];
        int c0 = q * 4;
        v.x = v.x * sA[c0] + sB[c0];         v.x = v.x > 0.f ? v.x : 0.01f * v.x;
        v.y = v.y * sA[c0 + 1] + sB[c0 + 1]; v.y = v.y > 0.f ? v.y : 0.01f * v.y;
        v.z = v.z * sA[c0 + 2] + sB[c0 + 2]; v.z = v.z > 0.f ? v.z : 0.01f * v.z;
        v.w = v.w * sA[c0 + 3] + sB[c0 + 3]; v.w = v.w > 0.f ? v.w : 0.01f * v.w;
        st[r * 33 + c0] = v.x; st[r * 33 + c0 + 1] = v.y;
        st[r * 33 + c0 + 2] = v.z; st[r * 33 + c0 + 3] = v.w;
    }
    __syncthreads();

    int w = threadIdx.x >> 5, lane = threadIdx.x & 31;
    int nn = nodeBase + lane;
    if (nn < N_NODES) {
#pragma unroll
        for (int j = 0; j < 4; j++) {
            int c = w * 4 + j;
            g_hT[(size_t)c * N_NODES + nn] = st[lane * 33 + c];   // coalesced
        }
    }
}

// ---------------------------------------------------------------------------
// Final: BN (no leaky) + prediction dot + scatter to graphs (batch is sorted).
// Tail lanes clamp and contribute 0 (all collectives full-warp).
// ---------------------------------------------------------------------------
__global__ void __launch_bounds__(256) k_fin(const int* __restrict__ batch,
                                             const float* __restrict__ pW,
                                             const float* __restrict__ bng,
                                             const float* __restrict__ bnb,
                                             float* out) {
    __shared__ float snorm[4 * C];
    __shared__ float spw[C];
    if (threadIdx.x < C) {
        float mu = g_stats[threadIdx.x] * (1.0f / N_NODES);
        float var = g_stats[C + threadIdx.x] * (1.0f / N_NODES) - mu * mu;
        snorm[threadIdx.x] = mu;
        snorm[C + threadIdx.x] = rsqrtf(var + BN_EPS);
        snorm[2 * C + threadIdx.x] = bng[threadIdx.x];
        snorm[3 * C + threadIdx.x] = bnb[threadIdx.x];
        spw[threadIdx.x] = pW[threadIdx.x];
    }
    __syncthreads();
    int n = blockIdx.x * blockDim.x + threadIdx.x;
    bool valid = n < N_NODES;
    int nn = valid ? n : N_NODES - 1;
    const float4* ap = (const float4*)(g_agg + (size_t)nn * C);
    float s = 0.f;
#pragma unroll
    for (int q = 0; q < 8; q++) {
        float4 v = ap[q];
        float t[4] = {v.x, v.y, v.z, v.w};
#pragma unroll
        for (int r = 0; r < 4; r++) {
            int c = 4 * q + r;
            float val = (t[r] - snorm[c]) * snorm[C + c] * snorm[2 * C + c] + snorm[3 * C + c];
            s += val * spw[c];
        }
    }
    if (!valid) s = 0.f;
    int bid = batch[nn];
    int bid0 = __shfl_sync(0xffffffffu, bid, 0);
    bool uni = __all_sync(0xffffffffu, bid == bid0 && valid);
    if (uni) {
#pragma unroll
        for (int off = 16; off >= 1; off >>= 1)
            s += __shfl_xor_sync(0xffffffffu, s, off);
        if ((threadIdx.x & 31) == 0) atomicAdd(&out[bid0], s);
    } else if (valid) {
        atomicAdd(&out[bid], s);
    }
}

// ---------------------------------------------------------------------------
extern "C" void kernel_launch(void* const* d_in, const int* in_sizes, int n_in,
                              void* d_out, int out_size) {
    const float* x       = (const float*)d_in[0];
    const int*   ei      = (const int*)d_in[1];
    const float* ea      = (const float*)d_in[2];
    const int*   batch   = (const int*)d_in[3];
    const float* lin_W   = (const float*)d_in[4];
    const float* lin_b   = (const float*)d_in[5];
    const float* mes_W1  = (const float*)d_in[6];
    const float* mes_b1  = (const float*)d_in[7];
    const float* mes_W2  = (const float*)d_in[8];
    const float* mes_b2  = (const float*)d_in[9];
    const float* root_W  = (const float*)d_in[10];
    const float* conv_b  = (const float*)d_in[11];
    const float* bn_g    = (const float*)d_in[12];
    const float* bn_b    = (const float*)d_in[13];
    const float* pred_W  = (const float*)d_in[14];
    const float* pred_b  = (const float*)d_in[15];
    float* out = (float*)d_out;

    const int* src = ei;
    const int* dst = ei + N_EDGES;

    int vwarps = 7 * ((N_NODES + 31) / 32);
    int vblocks = (vwarps + 7) / 8;                  // 1368
    int eblocks = (N_EDGES / 4 * 32 + 255) / 256;    // 6250
    int nblocks = (N_NODES + 31) / 32;               // 1563

    k_init<<<(N_NODES + 255) / 256, 256>>>(x, lin_W, lin_b);
    k_coef<<<(N_EDGES + 255) / 256, 256>>>(ea, mes_W1, mes_b1);
    for (int l = 0; l < NL; l++) {
        k_v<<<vblocks, 256>>>(mes_W2 + l * HID * C * C, mes_b2 + l * C * C,
                              root_W + l * C * C, conv_b + l * C);
        k_edge<<<eblocks, 256>>>(src, dst, l);
        k_stats<<<1184, 256>>>(out, pred_b, l == NL - 1 ? 1 : 0);
        if (l < NL - 1) k_normT<<<nblocks, 256>>>(bn_g + l * C, bn_b + l * C);
    }
    k_fin<<<(N_NODES + 255) / 256, 256>>>(batch, pred_W, bn_g + 2 * C, bn_b + 2 * C, out);
}